// round 16
// baseline (speedup 1.0000x reference)
#include <cuda_runtime.h>
#include <cuda_bf16.h>
#include <cstdint>

// Problem constants
#define BB   8
#define CC   64
#define NN   4096
#define OO   128
#define KNN  20

#define RESP 132      // gathermax result tile pitch
#define AP   72       // bf16 smem tile pitch (144B; conflict-free ldmatrix)

// single dynamic-smem symbol shared by all kernels
extern __shared__ char smem_dyn[];

// ---------------- scratch (static device globals; no allocation) -------------
__device__ float g_xx[BB * NN];                         // ||x_j||^2
__device__ float g_Ut[CC * 256];                        // combined weights [c][o']
__device__ float g_GT[(size_t)BB * NN * OO];            // G^T: [b][j][o]
__device__ float g_HT[(size_t)BB * NN * OO];            // H^T: [b][i][o]
__device__ int   g_idx[(size_t)BB * NN * KNN];          // knn indices
__device__ __nv_bfloat16 g_xt_hi[(size_t)BB * NN * CC]; // x^T split hi: [b][j][c]
__device__ __nv_bfloat16 g_xt_lo[(size_t)BB * NN * CC]; // x^T split lo: [b][j][c]

// ---------------- PTX helpers (base ISA only: ldmatrix + mma.sync) -----------
__device__ __forceinline__ uint32_t smem_u32(const void* p) {
    uint32_t a;
    asm("{ .reg .u64 t; cvta.to.shared.u64 t, %1; cvt.u32.u64 %0, t; }" : "=r"(a) : "l"(p));
    return a;
}
__device__ __forceinline__ void ldsm_x4(uint32_t* r, uint32_t addr) {
    asm volatile("ldmatrix.sync.aligned.m8n8.x4.shared.b16 {%0,%1,%2,%3}, [%4];"
                 : "=r"(r[0]), "=r"(r[1]), "=r"(r[2]), "=r"(r[3]) : "r"(addr));
}
__device__ __forceinline__ void mma16816(float* d, const uint32_t* a, const uint32_t* b) {
    asm volatile("mma.sync.aligned.m16n8k16.row.col.f32.bf16.bf16.f32 "
                 "{%0,%1,%2,%3}, {%4,%5,%6,%7}, {%8,%9}, {%0,%1,%2,%3};"
                 : "+f"(d[0]), "+f"(d[1]), "+f"(d[2]), "+f"(d[3])
                 : "r"(a[0]), "r"(a[1]), "r"(a[2]), "r"(a[3]), "r"(b[0]), "r"(b[1]));
}

// sorted-desc register top-20 insert (caller guarantees s > v[19])
__device__ __forceinline__ void insert20(float s, int j, float (&v)[20], int (&ix)[20]) {
    bool c[20];
#pragma unroll
    for (int q = 0; q < 20; ++q) c[q] = s > v[q];
#pragma unroll
    for (int q = 19; q >= 1; --q) {
        if (c[q]) {
            v[q]  = c[q - 1] ? v[q - 1] : s;
            ix[q] = c[q - 1] ? ix[q - 1] : j;
        }
    }
    if (c[0]) { v[0] = s; ix[0] = j; }
}

// ---------------- kernel 1: transpose + bf16 split + xx ----------------------
__global__ __launch_bounds__(256) void split_kernel(const float* __restrict__ x) {
    __shared__ float tile[64 * 68];
    __shared__ float part[64 * 4];
    int b = blockIdx.y, jbase = blockIdx.x * 64, t = threadIdx.x;
    const float* xb = x + (size_t)b * CC * NN;
    for (int k = t; k < 64 * 16; k += 256) {
        int c = k >> 4, p = k & 15;
        *(float4*)&tile[c * 68 + p * 4] = *(const float4*)&xb[c * NN + jbase + p * 4];
    }
    __syncthreads();
    int jl = t >> 2, g = t & 3;
    __nv_bfloat16 hi[16], lo[16];
    float ss = 0.f;
#pragma unroll
    for (int cc = 0; cc < 16; ++cc) {
        float v = tile[(g * 16 + cc) * 68 + jl];
        ss += v * v;
        __nv_bfloat16 h = __float2bfloat16(v);
        hi[cc] = h;
        lo[cc] = __float2bfloat16(v - __bfloat162float(h));
    }
    part[jl * 4 + g] = ss;
    size_t base = ((size_t)b * NN + jbase + jl) * CC + g * 16;
    *(uint4*)&g_xt_hi[base]     = *(uint4*)&hi[0];
    *(uint4*)&g_xt_hi[base + 8] = *(uint4*)&hi[8];
    *(uint4*)&g_xt_lo[base]     = *(uint4*)&lo[0];
    *(uint4*)&g_xt_lo[base + 8] = *(uint4*)&lo[8];
    __syncthreads();
    if (t < 64)
        g_xx[b * NN + jbase + t] = part[t * 4] + part[t * 4 + 1] + part[t * 4 + 2] + part[t * 4 + 3];
}

// ---------------- kernel 2: build combined weight Ut[c][o'] ------------------
__global__ void uprep_kernel(const float* __restrict__ W) {
    int c = blockIdx.x;
    int o = threadIdx.x;
    float v;
    if (o < OO) v = W[o * (2 * CC) + c];
    else {
        int oo = o - OO;
        v = W[oo * (2 * CC) + CC + c] - W[oo * (2 * CC) + c];
    }
    g_Ut[c * 256 + o] = v;
}

// ---------------- kernel 3: GH^T GEMM -> g_GT / g_HT -------------------------
__global__ __launch_bounds__(256) void gemm_gh_kernel(const float* __restrict__ x,
                                                      const float* __restrict__ bvec) {
    float* sm = (float*)smem_dyn;
    float* su = sm;                 // [64][256]
    float* sx = sm + CC * 256;      // [64][64]

    int b = blockIdx.y;
    int jbase = blockIdx.x * 64;
    int t = threadIdx.x;
    int tx = t & 7;
    int ty = t >> 3;

    const float4* ut4 = (const float4*)g_Ut;
    float4* su4 = (float4*)su;
    for (int k = t; k < CC * 256 / 4; k += 256) su4[k] = ut4[k];

    const float* xb = x + (size_t)b * CC * NN;
    for (int k = t; k < CC * 16; k += 256) {
        int c = k >> 4, p = k & 15;
        *(float4*)&sx[c * 64 + p * 4] = *(const float4*)&xb[c * NN + jbase + p * 4];
    }
    __syncthreads();

    float acc[8][8];
#pragma unroll
    for (int i = 0; i < 8; ++i)
#pragma unroll
        for (int j = 0; j < 8; ++j) acc[i][j] = 0.f;

#pragma unroll 4
    for (int c = 0; c < CC; ++c) {
        float4 a0 = *(float4*)&su[c * 256 + ty * 8];
        float4 a1 = *(float4*)&su[c * 256 + ty * 8 + 4];
        float4 b0 = *(float4*)&sx[c * 64 + tx * 8];
        float4 b1 = *(float4*)&sx[c * 64 + tx * 8 + 4];
        float aa[8] = {a0.x, a0.y, a0.z, a0.w, a1.x, a1.y, a1.z, a1.w};
        float bb[8] = {b0.x, b0.y, b0.z, b0.w, b1.x, b1.y, b1.z, b1.w};
#pragma unroll
        for (int i = 0; i < 8; ++i)
#pragma unroll
            for (int j = 0; j < 8; ++j) acc[i][j] += aa[i] * bb[j];
    }

    int obase = ty * 8;
    bool isH = (obase >= OO);
    float bias[8];
    if (isH) {
#pragma unroll
        for (int i = 0; i < 8; ++i) bias[i] = bvec[obase - OO + i];
    }
#pragma unroll
    for (int jq = 0; jq < 8; ++jq) {
        int j = jbase + tx * 8 + jq;
        float* dst = isH ? &g_HT[((size_t)b * NN + j) * OO + (obase - OO)]
                         : &g_GT[((size_t)b * NN + j) * OO + obase];
#pragma unroll
        for (int i = 0; i < 8; ++i) {
            float v = acc[i][jq];
            if (isH) v += bias[i];
            dst[i] = v;
        }
    }
}

// ---------------- kernel 4: HMMA distance GEMM + register top-20 -------------
// 256 threads (8 warps). Warp w: rows [16w,16w+16). j in 64-chunks, B double-buf.
// K=64, 4-term bf16 split, EXACT fp32 xx subtraction at filter time.
// R13: ONE top-20 list per row. After the fragment swap, the even-pair lane
// (lane&2 == 0) gathers the partner lane's 4 columns (2 more SHFL xor 2 per
// half) and owns all 8 columns per nj; only 16 lanes/warp run the insert path
// (union of divergent inserts shrinks), and the end-of-kernel pair-merge is
// deleted (direct global write).
#define A_TILE (128 * AP * 2)            // 18432 bytes per A sub-tile
#define B_TILE (64 * AP * 2)             // 9216 bytes per B sub-tile
#define OFF_AHI 0
#define OFF_ALO A_TILE                   // 18432
#define OFF_B   (2 * A_TILE)             // 36864
#define B_BUF_STRIDE (2 * B_TILE)        // 18432 (hi at +0, lo at +B_TILE)
#define OFF_NXX (OFF_B + 2 * B_BUF_STRIDE)    // 73728 (2 bufs x 64 floats)
#define KNN_SMEM (OFF_NXX + 2 * 64 * 4)       // 74240 bytes

__device__ __forceinline__ void load_b_tile(char* sm, int b, int jbase, int buf, int t) {
    __nv_bfloat16* bh = (__nv_bfloat16*)(sm + OFF_B + buf * B_BUF_STRIDE);
    __nv_bfloat16* bl = (__nv_bfloat16*)(sm + OFF_B + buf * B_BUF_STRIDE + B_TILE);
    const uint4* srcH = (const uint4*)(g_xt_hi + ((size_t)b * NN + jbase) * CC);
    const uint4* srcL = (const uint4*)(g_xt_lo + ((size_t)b * NN + jbase) * CC);
#pragma unroll
    for (int it = 0; it < 2; ++it) {
        int k = t + it * 256;
        int row = k >> 3, p = k & 7;
        *(uint4*)&bh[row * AP + p * 8] = srcH[k];
        *(uint4*)&bl[row * AP + p * 8] = srcL[k];
    }
    if (t >= 64 && t < 128) {
        int r = t - 64;
        ((float*)(sm + OFF_NXX))[buf * 64 + r] = -g_xx[b * NN + jbase + r];
    }
}

__global__ __launch_bounds__(256, 2) void knn_kernel() {
    char* sm = smem_dyn;
    uint32_t sbase = smem_u32(sm);
    int t = threadIdx.x;
    int warp = t >> 5, lane = t & 31;
    int gid = lane >> 2, tig = lane & 3;
    int b = blockIdx.y;
    int ibase = blockIdx.x * 128;
    int mrow0 = warp * 16;

    __nv_bfloat16* sAhi = (__nv_bfloat16*)(sm + OFF_AHI);
    __nv_bfloat16* sAlo = (__nv_bfloat16*)(sm + OFF_ALO);
    float* nxx = (float*)(sm + OFF_NXX);

    // A data
    {
        const uint4* srcH = (const uint4*)(g_xt_hi + ((size_t)b * NN + ibase) * CC);
        const uint4* srcL = (const uint4*)(g_xt_lo + ((size_t)b * NN + ibase) * CC);
#pragma unroll
        for (int it = 0; it < 4; ++it) {
            int k = t + it * 256;
            int row = k >> 3, p = k & 7;
            *(uint4*)&sAhi[row * AP + p * 8] = srcH[k];
            *(uint4*)&sAlo[row * AP + p * 8] = srcL[k];
        }
    }
    load_b_tile(sm, b, 0, 0, t);   // preload chunk 0

    // register top-20 (sorted desc) + local pending stack (active lanes only)
    float v[20]; int ixr[20];
#pragma unroll
    for (int q = 0; q < 20; ++q) { v[q] = -3.4e38f; ixr[q] = 0; }
    float pend_s[40]; int pend_j[40]; int cnt = 0;

    // ldmatrix lane address components
    int arow = (lane & 7) + 8 * ((lane >> 3) & 1);
    int asel = 8 * (lane >> 4);
    int brow = ((lane >> 4) & 1) * 8 + (lane & 7);
    int bsel = 8 * ((lane >> 3) & 1);
    bool oddh = tig & 1;
    bool active = (lane & 2) == 0;              // even-pair lane owns full row
    int rloc = mrow0 + gid + 8 * (tig & 1);     // row this lane's candidates belong to

    for (int ch = 0; ch < 64; ++ch) {
        __syncthreads();   // B[ch]+nxx[ch] ready; all warps done with iter ch-1
        int curb = ch & 1;
        if (ch < 63) load_b_tile(sm, b, (ch + 1) * 64, curb ^ 1, t);

        float acc[8][4];
#pragma unroll
        for (int nj = 0; nj < 8; ++nj)
#pragma unroll
            for (int q = 0; q < 4; ++q) acc[nj][q] = 0.f;

#pragma unroll
        for (int ks = 0; ks < 4; ++ks) {
            int kc = ks * 16;
            uint32_t ah[4], al[4];
            uint32_t aoff = sbase + OFF_AHI + ((mrow0 + arow) * AP + kc + asel) * 2;
            ldsm_x4(ah, aoff);
            ldsm_x4(al, aoff + A_TILE);
#pragma unroll
            for (int njp = 0; njp < 4; ++njp) {
                uint32_t bh4[4], bl4[4];
                uint32_t boff = sbase + OFF_B + curb * B_BUF_STRIDE
                              + ((njp * 16 + brow) * AP + kc + bsel) * 2;
                ldsm_x4(bh4, boff);
                ldsm_x4(bl4, boff + B_TILE);
                mma16816(acc[njp * 2], ah, bh4);
                mma16816(acc[njp * 2], ah, bl4);
                mma16816(acc[njp * 2], al, bh4);
                mma16816(acc[njp * 2], al, bl4);
                mma16816(acc[njp * 2 + 1], ah, bh4 + 2);
                mma16816(acc[njp * 2 + 1], ah, bl4 + 2);
                mma16816(acc[njp * 2 + 1], al, bh4 + 2);
                mma16816(acc[njp * 2 + 1], al, bl4 + 2);
            }
        }

        float thr = v[19];          // exact row threshold (active lanes)
        const float* nxc = nxx + curb * 64;
#pragma unroll
        for (int nj = 0; nj < 8; ++nj) {
            // swap 1: lane owns ONE row, 4 consecutive cols (colbase by tig>>1)
            float d0 = acc[nj][0], d1 = acc[nj][1], d2 = acc[nj][2], d3 = acc[nj][3];
            float r0 = __shfl_xor_sync(0xffffffffu, oddh ? d0 : d2, 1);
            float r1 = __shfl_xor_sync(0xffffffffu, oddh ? d1 : d3, 1);
            float c0 = oddh ? r0 : d0;
            float c1 = oddh ? r1 : d1;
            float c2 = oddh ? d2 : r0;
            float c3 = oddh ? d3 : r1;
            int jc = nj * 8;        // active lane covers all 8 cols of this group
            float4 nxa = *(const float4*)&nxc[jc];
            float4 nxb = *(const float4*)&nxc[jc + 4];
            // own half scores (active lane: cols 0..3 of group)
            float s0 = fmaf(2.f, c0, active ? nxa.x : nxb.x);
            float s1 = fmaf(2.f, c1, active ? nxa.y : nxb.y);
            float s2 = fmaf(2.f, c2, active ? nxa.z : nxb.z);
            float s3 = fmaf(2.f, c3, active ? nxa.w : nxb.w);
            // swap 2: gather partner half (lane^2 same row, other 4 cols)
            float p0 = __shfl_xor_sync(0xffffffffu, s0, 2);
            float p1 = __shfl_xor_sync(0xffffffffu, s1, 2);
            float p2 = __shfl_xor_sync(0xffffffffu, s2, 2);
            float p3 = __shfl_xor_sync(0xffffffffu, s3, 2);
            if (active) {
                float gmax = fmaxf(fmaxf(fmaxf(s0, s1), fmaxf(s2, s3)),
                                   fmaxf(fmaxf(p0, p1), fmaxf(p2, p3)));
                if (gmax > thr) {
                    int j0 = ch * 64 + jc;
                    if (s0 > thr) { pend_s[cnt] = s0; pend_j[cnt] = j0;     ++cnt; }
                    if (s1 > thr) { pend_s[cnt] = s1; pend_j[cnt] = j0 + 1; ++cnt; }
                    if (s2 > thr) { pend_s[cnt] = s2; pend_j[cnt] = j0 + 2; ++cnt; }
                    if (s3 > thr) { pend_s[cnt] = s3; pend_j[cnt] = j0 + 3; ++cnt; }
                    if (p0 > thr) { pend_s[cnt] = p0; pend_j[cnt] = j0 + 4; ++cnt; }
                    if (p1 > thr) { pend_s[cnt] = p1; pend_j[cnt] = j0 + 5; ++cnt; }
                    if (p2 > thr) { pend_s[cnt] = p2; pend_j[cnt] = j0 + 6; ++cnt; }
                    if (p3 > thr) { pend_s[cnt] = p3; pend_j[cnt] = j0 + 7; ++cnt; }
                    // overflow guard: next nj adds <=8; keep cnt <= 32 here
                    if (cnt >= 32) {
                        for (int u = 0; u < cnt; ++u) {
                            float s = pend_s[u];
                            if (s > v[19]) insert20(s, pend_j[u], v, ixr);
                        }
                        cnt = 0;
                        thr = v[19];
                    }
                }
            }
        }
        // batch drain
        if (cnt >= 8) {
            for (int u = 0; u < cnt; ++u) {
                float s = pend_s[u];
                if (s > v[19]) insert20(s, pend_j[u], v, ixr);
            }
            cnt = 0;
        }
    }
    // final drain + direct output (active lanes own complete per-row lists)
    if (active) {
        for (int u = 0; u < cnt; ++u) {
            float s = pend_s[u];
            if (s > v[19]) insert20(s, pend_j[u], v, ixr);
        }
        int* dst = &g_idx[((size_t)b * NN + ibase + rloc) * KNN];
#pragma unroll
        for (int k = 0; k < KNN; ++k) dst[k] = ixr[k];
    }
}

// ---------------- kernel 5: gather-max + leaky + transposed write ------------
__global__ __launch_bounds__(256) void gathermax_kernel(float* __restrict__ out) {
    __shared__ int   sidx[32 * KNN];
    __shared__ float sres[32 * RESP];
    int b = blockIdx.y;
    int ibase = blockIdx.x * 32;
    int t = threadIdx.x;
    int w = t >> 5;
    int l = t & 31;

    for (int k = t; k < 32 * KNN; k += 256)
        sidx[k] = g_idx[((size_t)b * NN + ibase) * KNN + k];
    __syncthreads();

    const float* GTb = g_GT + (size_t)b * NN * OO;
    const float* HTb = g_HT + (size_t)b * NN * OO;

#pragma unroll
    for (int p = 0; p < 4; ++p) {
        int pp = w * 4 + p;
        int i = ibase + pp;
        float4 m = make_float4(-3.4e38f, -3.4e38f, -3.4e38f, -3.4e38f);
#pragma unroll
        for (int k = 0; k < KNN; ++k) {
            int j = sidx[pp * KNN + k];
            float4 g = *(const float4*)&GTb[(size_t)j * OO + l * 4];
            m.x = fmaxf(m.x, g.x); m.y = fmaxf(m.y, g.y);
            m.z = fmaxf(m.z, g.z); m.w = fmaxf(m.w, g.w);
        }
        float4 h = *(const float4*)&HTb[(size_t)i * OO + l * 4];
        float v0 = m.x + h.x, v1 = m.y + h.y, v2 = m.z + h.z, v3 = m.w + h.w;
        v0 = v0 >= 0.f ? v0 : 0.2f * v0;
        v1 = v1 >= 0.f ? v1 : 0.2f * v1;
        v2 = v2 >= 0.f ? v2 : 0.2f * v2;
        v3 = v3 >= 0.f ? v3 : 0.2f * v3;
        *(float4*)&sres[pp * RESP + l * 4] = make_float4(v0, v1, v2, v3);
    }
    __syncthreads();

    float* ob = out + (size_t)b * OO * NN;
    for (int k = t; k < OO * 32; k += 256) {
        int o = k >> 5, ii = k & 31;
        ob[(size_t)o * NN + ibase + ii] = sres[ii * RESP + o];
    }
}

// ---------------- launch ------------------------------------------------------
extern "C" void kernel_launch(void* const* d_in, const int* in_sizes, int n_in,
                              void* d_out, int out_size) {
    const float* x    = (const float*)d_in[0];   // (8, 64, 4096)
    const float* W    = (const float*)d_in[1];   // (128, 128)
    const float* bvec = (const float*)d_in[2];   // (128,)
    float* out = (float*)d_out;                  // (8, 128, 4096)

    const int SMEM_GEMM = (CC * 256 + CC * 64) * 4;   // 80KB
    cudaFuncSetAttribute(gemm_gh_kernel, cudaFuncAttributeMaxDynamicSharedMemorySize, SMEM_GEMM);
    cudaFuncSetAttribute(knn_kernel,     cudaFuncAttributeMaxDynamicSharedMemorySize, KNN_SMEM);

    split_kernel<<<dim3(NN / 64, BB), 256>>>(x);
    uprep_kernel<<<CC, 256>>>(W);
    gemm_gh_kernel<<<dim3(NN / 64, BB), 256, SMEM_GEMM>>>(x, bvec);
    knn_kernel<<<dim3(NN / 128, BB), 256, KNN_SMEM>>>();
    gathermax_kernel<<<dim3(NN / 32, BB), 256>>>(out);
}